// round 2
// baseline (speedup 1.0000x reference)
#include <cuda_runtime.h>
#include <cuda_bf16.h>
#include <cstdint>
#include <cstddef>

// Problem constants
#define NTOK   8192      // 8*1024 tokens
#define DIM    512
#define NG     20
#define NLAT   10000
#define NLATP  10112     // padded to 79*128 for tiling; pad columns are zero
#define PAD_TOK 1

// Scratch (device globals; no runtime allocations allowed)
__device__ __nv_bfloat16 g_Q[NTOK * DIM];                 // lang_emb bf16
__device__ float         g_lang[NTOK * DIM];              // lang_emb fp32
__device__ __nv_bfloat16 g_Lb[NLAT * DIM];                // latent_mat bf16
__device__ __nv_bfloat16 g_E[(size_t)NTOK * NLATP];       // exp(scores) bf16
__device__ float         g_den[NTOK];                     // softmax denominators

// ---------------- PTX helpers ----------------

__device__ __forceinline__ void mma_bf16(float* c, const uint32_t* a, const uint32_t* b) {
    asm volatile(
        "mma.sync.aligned.m16n8k16.row.col.f32.bf16.bf16.f32 "
        "{%0,%1,%2,%3}, {%4,%5,%6,%7}, {%8,%9}, {%0,%1,%2,%3};\n"
        : "+f"(c[0]), "+f"(c[1]), "+f"(c[2]), "+f"(c[3])
        : "r"(a[0]), "r"(a[1]), "r"(a[2]), "r"(a[3]),
          "r"(b[0]), "r"(b[1]));
}

__device__ __forceinline__ void ldsm4(uint32_t* r, uint32_t addr) {
    asm volatile("ldmatrix.sync.aligned.m8n8.x4.shared.b16 {%0,%1,%2,%3}, [%4];\n"
                 : "=r"(r[0]), "=r"(r[1]), "=r"(r[2]), "=r"(r[3]) : "r"(addr));
}

__device__ __forceinline__ void ldsm4t(uint32_t* r, uint32_t addr) {
    asm volatile("ldmatrix.sync.aligned.m8n8.x4.trans.shared.b16 {%0,%1,%2,%3}, [%4];\n"
                 : "=r"(r[0]), "=r"(r[1]), "=r"(r[2]), "=r"(r[3]) : "r"(addr));
}

__device__ __forceinline__ void cp16(uint32_t dst, const void* src, int sz) {
    asm volatile("cp.async.cg.shared.global [%0], [%1], 16, %2;\n"
                 :: "r"(dst), "l"(src), "r"(sz));
}
#define CP_COMMIT()  asm volatile("cp.async.commit_group;\n" ::: "memory")
#define CP_WAIT(N)   asm volatile("cp.async.wait_group " #N ";\n" ::: "memory")

// ---------------- Kernel 1: lang_emb = tanh(masked ngram sum) ----------------

__global__ void lang_kernel(const int* __restrict__ x, const float* __restrict__ ct) {
    int tok = blockIdx.x;
    int d = threadIdx.x * 4;                 // 128 threads * 4 = 512
    const int* xr = x + (size_t)tok * NG;
    float4 acc = make_float4(0.f, 0.f, 0.f, 0.f);
#pragma unroll
    for (int g = 0; g < NG; g++) {
        int idx = xr[g];
        if (idx != PAD_TOK) {
            float4 v = *(const float4*)(ct + (size_t)idx * DIM + d);
            acc.x += v.x; acc.y += v.y; acc.z += v.z; acc.w += v.w;
        }
    }
    float4 t;
    t.x = tanhf(acc.x); t.y = tanhf(acc.y); t.z = tanhf(acc.z); t.w = tanhf(acc.w);
    *(float4*)(g_lang + (size_t)tok * DIM + d) = t;
    __nv_bfloat162 p0 = __floats2bfloat162_rn(t.x, t.y);
    __nv_bfloat162 p1 = __floats2bfloat162_rn(t.z, t.w);
    *(__nv_bfloat162*)(g_Q + (size_t)tok * DIM + d)     = p0;
    *(__nv_bfloat162*)(g_Q + (size_t)tok * DIM + d + 2) = p1;
}

// ---------------- Kernel 2: latent_mat -> bf16 ----------------

__global__ void cvt_latent(const float* __restrict__ lm) {
    int base = (blockIdx.x * blockDim.x + threadIdx.x) * 4;
    if (base < NLAT * DIM) {
        float4 v = *(const float4*)(lm + base);
        *(__nv_bfloat162*)(g_Lb + base)     = __floats2bfloat162_rn(v.x, v.y);
        *(__nv_bfloat162*)(g_Lb + base + 2) = __floats2bfloat162_rn(v.z, v.w);
    }
}

// ---------------- GEMM1: E = exp(Q @ L^T), bf16 out ----------------
// A = g_Q [8192,512] row-major; B = g_Lb [N=10000(+pad),K=512] K-major.
// CTA 128x128, BK=32, 8 warps (4 M x 2 N), warp tile 32x64.

__global__ __launch_bounds__(256, 1) void gemm1_kernel() {
    constexpr int LDA = 40;   // padded bf16 stride -> conflict-free ldmatrix
    __shared__ __nv_bfloat16 sA[2][128 * LDA];
    __shared__ __nv_bfloat16 sB[2][128 * LDA];

    const int tid = threadIdx.x, lane = tid & 31, wid = tid >> 5;
    const int wm = wid & 3, wn = wid >> 2;
    const int bm = blockIdx.y * 128, bn = blockIdx.x * 128;
    const uint32_t sAu = (uint32_t)__cvta_generic_to_shared(&sA[0][0]);
    const uint32_t sBu = (uint32_t)__cvta_generic_to_shared(&sB[0][0]);

    float c[2][8][4];
#pragma unroll
    for (int i = 0; i < 2; i++)
#pragma unroll
        for (int j = 0; j < 8; j++)
#pragma unroll
            for (int k = 0; k < 4; k++) c[i][j][k] = 0.f;

    const int nk = DIM / 32;  // 16

    auto load_tiles = [&](int s, int kt) {
        int k0 = kt * 32;
#pragma unroll
        for (int i = 0; i < 2; i++) {
            int lin = tid * 2 + i;            // 0..511 chunks of 8 bf16
            int row = lin >> 2, cc = lin & 3;
            const __nv_bfloat16* srcA = g_Q + (size_t)(bm + row) * DIM + k0 + cc * 8;
            cp16(sAu + (uint32_t)(s * 128 * LDA + row * LDA + cc * 8) * 2, srcA, 16);
            int nrow = bn + row;
            int ok = (nrow < NLAT);
            const __nv_bfloat16* srcB = g_Lb + (size_t)(ok ? nrow : 0) * DIM + k0 + cc * 8;
            cp16(sBu + (uint32_t)(s * 128 * LDA + row * LDA + cc * 8) * 2, srcB, ok ? 16 : 0);
        }
        CP_COMMIT();
    };

    load_tiles(0, 0);
    for (int kt = 0; kt < nk; kt++) {
        if (kt + 1 < nk) { load_tiles((kt + 1) & 1, kt + 1); CP_WAIT(1); }
        else             { CP_WAIT(0); }
        __syncthreads();
        int s = kt & 1;

        uint32_t b[8][4];
#pragma unroll
        for (int nf = 0; nf < 8; nf++) {
            uint32_t addr = sBu + (uint32_t)(s * 128 * LDA +
                             (wn * 64 + nf * 8 + (lane & 7)) * LDA + (lane >> 3) * 8) * 2;
            ldsm4(b[nf], addr);
        }
#pragma unroll
        for (int kh = 0; kh < 2; kh++) {
            uint32_t a[2][4];
#pragma unroll
            for (int mf = 0; mf < 2; mf++) {
                uint32_t addr = sAu + (uint32_t)(s * 128 * LDA +
                                 (wm * 32 + mf * 16 + (lane & 15)) * LDA +
                                 kh * 16 + ((lane >> 4) & 1) * 8) * 2;
                ldsm4(a[mf], addr);
            }
#pragma unroll
            for (int mf = 0; mf < 2; mf++)
#pragma unroll
                for (int nf = 0; nf < 8; nf++)
                    mma_bf16(c[mf][nf], a[mf], &b[nf][kh * 2]);
        }
        __syncthreads();
    }

    // Epilogue: exp (scores |s| <~ 0.3, no max-shift needed), zero pad columns.
    const int tg = lane >> 2, tig = lane & 3;
#pragma unroll
    for (int mf = 0; mf < 2; mf++) {
#pragma unroll
        for (int nf = 0; nf < 8; nf++) {
            int r = bm + wm * 32 + mf * 16 + tg;
            int n = bn + wn * 64 + nf * 8 + tig * 2;
            bool v = (n < NLAT);   // n even, NLAT even -> pair in/out together
            float e0 = v ? __expf(c[mf][nf][0]) : 0.f;
            float e1 = v ? __expf(c[mf][nf][1]) : 0.f;
            float e2 = v ? __expf(c[mf][nf][2]) : 0.f;
            float e3 = v ? __expf(c[mf][nf][3]) : 0.f;
            *(__nv_bfloat162*)(g_E + (size_t)r * NLATP + n)       = __floats2bfloat162_rn(e0, e1);
            *(__nv_bfloat162*)(g_E + (size_t)(r + 8) * NLATP + n) = __floats2bfloat162_rn(e2, e3);
        }
    }
}

// ---------------- Kernel 4: row sums of E (deterministic) ----------------

__global__ void rowsum_kernel() {
    int r = blockIdx.x;
    const __nv_bfloat162* row = (const __nv_bfloat162*)(g_E + (size_t)r * NLATP);
    float s = 0.f;
    for (int i = threadIdx.x; i < NLATP / 2; i += blockDim.x) {
        float2 v = __bfloat1622float2(row[i]);
        s += v.x + v.y;
    }
#pragma unroll
    for (int o = 16; o; o >>= 1) s += __shfl_xor_sync(0xffffffffu, s, o);
    __shared__ float red[8];
    if ((threadIdx.x & 31) == 0) red[threadIdx.x >> 5] = s;
    __syncthreads();
    if (threadIdx.x < 8) {
        float t = red[threadIdx.x];
#pragma unroll
        for (int o = 4; o; o >>= 1) t += __shfl_xor_sync(0xffu, t, o);
        if (threadIdx.x == 0) g_den[r] = t;
    }
}

// ---------------- GEMM2: out = lang + (E @ L)/den, + first-token override ----------------
// A = g_E [8192, NLATP] row-major; B = g_Lb [K=10000(+pad), N=512] N-contiguous (ldmatrix.trans).

__global__ __launch_bounds__(256, 1) void gemm2_kernel(const int* __restrict__ x,
                                                       const float* __restrict__ ct,
                                                       float* __restrict__ out) {
    constexpr int LDA = 40, LDB = 136;  // padded bf16 strides
    __shared__ __nv_bfloat16 sA[2][128 * LDA];
    __shared__ __nv_bfloat16 sB[2][32 * LDB];

    const int tid = threadIdx.x, lane = tid & 31, wid = tid >> 5;
    const int wm = wid & 3, wn = wid >> 2;
    const int bm = blockIdx.y * 128, bn = blockIdx.x * 128;
    const uint32_t sAu = (uint32_t)__cvta_generic_to_shared(&sA[0][0]);
    const uint32_t sBu = (uint32_t)__cvta_generic_to_shared(&sB[0][0]);

    float c[2][8][4];
#pragma unroll
    for (int i = 0; i < 2; i++)
#pragma unroll
        for (int j = 0; j < 8; j++)
#pragma unroll
            for (int k = 0; k < 4; k++) c[i][j][k] = 0.f;

    const int nk = NLATP / 32;  // 316

    auto load_tiles = [&](int s, int kt) {
        int k0 = kt * 32;
#pragma unroll
        for (int i = 0; i < 2; i++) {
            int lin = tid * 2 + i;
            // A: 128 rows x 32 cols
            int row = lin >> 2, cc = lin & 3;
            const __nv_bfloat16* srcA = g_E + (size_t)(bm + row) * NLATP + k0 + cc * 8;
            cp16(sAu + (uint32_t)(s * 128 * LDA + row * LDA + cc * 8) * 2, srcA, 16);
            // B: 32 k-rows x 128 n-cols
            int krow = lin >> 4, nc = lin & 15;
            int kk = k0 + krow;
            int ok = (kk < NLAT);
            const __nv_bfloat16* srcB = g_Lb + (size_t)(ok ? kk : 0) * DIM + bn + nc * 8;
            cp16(sBu + (uint32_t)(s * 32 * LDB + krow * LDB + nc * 8) * 2, srcB, ok ? 16 : 0);
        }
        CP_COMMIT();
    };

    load_tiles(0, 0);
    for (int kt = 0; kt < nk; kt++) {
        if (kt + 1 < nk) { load_tiles((kt + 1) & 1, kt + 1); CP_WAIT(1); }
        else             { CP_WAIT(0); }
        __syncthreads();
        int s = kt & 1;

        uint32_t b[8][4];
#pragma unroll
        for (int nf = 0; nf < 8; nf++) {
            uint32_t addr = sBu + (uint32_t)(s * 32 * LDB + lane * LDB +
                             wn * 64 + nf * 8) * 2;
            ldsm4t(b[nf], addr);
        }
#pragma unroll
        for (int kh = 0; kh < 2; kh++) {
            uint32_t a[2][4];
#pragma unroll
            for (int mf = 0; mf < 2; mf++) {
                uint32_t addr = sAu + (uint32_t)(s * 128 * LDA +
                                 (wm * 32 + mf * 16 + (lane & 15)) * LDA +
                                 kh * 16 + ((lane >> 4) & 1) * 8) * 2;
                ldsm4(a[mf], addr);
            }
#pragma unroll
            for (int mf = 0; mf < 2; mf++)
#pragma unroll
                for (int nf = 0; nf < 8; nf++)
                    mma_bf16(c[mf][nf], a[mf], &b[nf][kh * 2]);
        }
        __syncthreads();
    }

    // Epilogue: divide by softmax denominator, add lang, apply token override.
    const int tg = lane >> 2, tig = lane & 3;
#pragma unroll
    for (int mf = 0; mf < 2; mf++) {
        int r0 = bm + wm * 32 + mf * 16 + tg;
        int r1 = r0 + 8;
        float di0 = 1.f / g_den[r0];
        float di1 = 1.f / g_den[r1];
        unsigned f0 = (unsigned)x[(size_t)r0 * NG];
        unsigned f1 = (unsigned)x[(size_t)r1 * NG];
#pragma unroll
        for (int nf = 0; nf < 8; nf++) {
            int cc = bn + wn * 64 + nf * 8 + tig * 2;
            float2 o0, o1;
            if (f0 <= 3u) {
                o0.x = ct[(size_t)f0 * DIM + cc];
                o0.y = ct[(size_t)f0 * DIM + cc + 1];
            } else {
                o0.x = c[mf][nf][0] * di0 + g_lang[(size_t)r0 * DIM + cc];
                o0.y = c[mf][nf][1] * di0 + g_lang[(size_t)r0 * DIM + cc + 1];
            }
            if (f1 <= 3u) {
                o1.x = ct[(size_t)f1 * DIM + cc];
                o1.y = ct[(size_t)f1 * DIM + cc + 1];
            } else {
                o1.x = c[mf][nf][2] * di1 + g_lang[(size_t)r1 * DIM + cc];
                o1.y = c[mf][nf][3] * di1 + g_lang[(size_t)r1 * DIM + cc + 1];
            }
            *(float2*)(out + (size_t)r0 * DIM + cc) = o0;
            *(float2*)(out + (size_t)r1 * DIM + cc) = o1;
        }
    }
}

// ---------------- launch ----------------

extern "C" void kernel_launch(void* const* d_in, const int* in_sizes, int n_in,
                              void* d_out, int out_size) {
    const int*   x  = (const int*)d_in[0];
    const float* ct = (const float*)d_in[1];
    const float* lm = (const float*)d_in[2];
    float* out = (float*)d_out;

    lang_kernel<<<NTOK, 128>>>(x, ct);
    cvt_latent<<<(NLAT * DIM) / (4 * 256), 256>>>(lm);
    gemm1_kernel<<<dim3(NLATP / 128, NTOK / 128), 256>>>();
    rowsum_kernel<<<NTOK, 256>>>();
    gemm2_kernel<<<dim3(DIM / 128, NTOK / 128), 256>>>(x, ct, out);
}

// round 8
// speedup vs baseline: 1.4880x; 1.4880x over previous
#include <cuda_runtime.h>
#include <cuda_bf16.h>
#include <cstdint>
#include <cstddef>

// Problem constants
#define NTOK    8192
#define DIM     512
#define NG      20
#define NLAT    10000
#define NLATP   10240          // padded to 80*128
#define NB1     80             // GEMM1 n-blocks (128 wide)
#define PAD_TOK 1

// Scales: Q*32, L*256 -> scores*8192 ; E stored *32, LT *256 -> gemm2 acc *8192
#define INV_8192 (1.220703125e-4f)

// Scratch (device globals; no runtime allocations allowed)
__device__ uint8_t g_Q8[NTOK * DIM];                 // fp8(e4m3) of 32*lang
__device__ float   g_lang[NTOK * DIM];               // lang fp32
__device__ uint8_t g_L8[NLAT * DIM];                 // fp8 of 256*L, [l][d]
__device__ uint8_t g_LT8[DIM * NLATP];               // fp8 of 256*L, [d][l] (pad zeros)
__device__ uint8_t g_E8[(size_t)NTOK * NLATP];       // fp8 of 32*exp(score) (pad zeros)
__device__ float   g_part[(size_t)NTOK * NB1];       // rowsum partials (fp32, exact e)
__device__ float   g_den[NTOK];                      // softmax denominators

// ---------------- helpers ----------------

__device__ __forceinline__ void mma_e4m3(float* c, const uint32_t* a, const uint32_t* b) {
    asm volatile(
        "mma.sync.aligned.m16n8k32.row.col.f32.e4m3.e4m3.f32 "
        "{%0,%1,%2,%3}, {%4,%5,%6,%7}, {%8,%9}, {%0,%1,%2,%3};\n"
        : "+f"(c[0]), "+f"(c[1]), "+f"(c[2]), "+f"(c[3])
        : "r"(a[0]), "r"(a[1]), "r"(a[2]), "r"(a[3]),
          "r"(b[0]), "r"(b[1]));
}

__device__ __forceinline__ void ldsm4(uint32_t* r, uint32_t addr) {
    asm volatile("ldmatrix.sync.aligned.m8n8.x4.shared.b16 {%0,%1,%2,%3}, [%4];\n"
                 : "=r"(r[0]), "=r"(r[1]), "=r"(r[2]), "=r"(r[3]) : "r"(addr));
}

__device__ __forceinline__ void cp16(uint32_t dst, const void* src, int sz) {
    asm volatile("cp.async.cg.shared.global [%0], [%1], 16, %2;\n"
                 :: "r"(dst), "l"(src), "r"(sz));
}
#define CP_COMMIT()  asm volatile("cp.async.commit_group;\n" ::: "memory")
#define CP_WAIT2()   asm volatile("cp.async.wait_group 2;\n" ::: "memory")
#define CP_WAIT1()   asm volatile("cp.async.wait_group 1;\n" ::: "memory")
#define CP_WAIT0()   asm volatile("cp.async.wait_group 0;\n" ::: "memory")

// pack two fp32 -> e4m3x2 (lo = low byte / lower address)
__device__ __forceinline__ uint16_t pack_e4m3x2(float hi, float lo) {
    uint16_t r;
    asm("cvt.rn.satfinite.e4m3x2.f32 %0, %1, %2;" : "=h"(r) : "f"(hi), "f"(lo));
    return r;
}
__device__ __forceinline__ uint8_t pack_e4m3(float v) {
    return (uint8_t)(pack_e4m3x2(0.f, v) & 0xFF);
}

// fast exp without MUFU: exp2-style range reduction + deg-5 Taylor (|f|<=0.347)
__device__ __forceinline__ float fast_exp(float s) {
    float t = s * 1.44269504f;
    float n = rintf(t);
    float f = (t - n) * 0.69314718f;
    float p = 1.f + f * (1.f + f * (0.5f + f * (0.16666667f +
              f * (0.04166667f + f * 0.00833333f))));
    int ni = (int)n;
    return __int_as_float(__float_as_int(p) + (ni << 23));
}

// ---------------- lang = tanh(masked ngram sum); Q8 = fp8(32*lang) ----------------

__global__ void lang_kernel(const int* __restrict__ x, const float* __restrict__ ct) {
    int tok = blockIdx.x;
    int d = threadIdx.x * 4;
    const int* xr = x + (size_t)tok * NG;
    float4 acc = make_float4(0.f, 0.f, 0.f, 0.f);
#pragma unroll
    for (int g = 0; g < NG; g++) {
        int idx = xr[g];
        if (idx != PAD_TOK) {
            float4 v = *(const float4*)(ct + (size_t)idx * DIM + d);
            acc.x += v.x; acc.y += v.y; acc.z += v.z; acc.w += v.w;
        }
    }
    float4 t;
    t.x = tanhf(acc.x); t.y = tanhf(acc.y); t.z = tanhf(acc.z); t.w = tanhf(acc.w);
    *(float4*)(g_lang + (size_t)tok * DIM + d) = t;
    uint32_t p = (uint32_t)pack_e4m3x2(t.y * 32.f, t.x * 32.f)
               | ((uint32_t)pack_e4m3x2(t.w * 32.f, t.z * 32.f) << 16);
    *(uint32_t*)(g_Q8 + (size_t)tok * DIM + d) = p;
}

// ---------------- latent -> fp8 row-major [l][d] ----------------

__global__ void cvt_latent8(const float* __restrict__ lm) {
    int base = (blockIdx.x * blockDim.x + threadIdx.x) * 4;
    if (base < NLAT * DIM) {
        float4 v = *(const float4*)(lm + base);
        uint32_t p = (uint32_t)pack_e4m3x2(v.y * 256.f, v.x * 256.f)
                   | ((uint32_t)pack_e4m3x2(v.w * 256.f, v.z * 256.f) << 16);
        *(uint32_t*)(g_L8 + base) = p;
    }
}

// ---------------- latent transpose -> fp8 [d][NLATP] ----------------

__global__ void transpose_latent8(const float* __restrict__ lm) {
    __shared__ float t[32][33];
    int tx = threadIdx.x, ty = threadIdx.y;     // 32 x 8
    int l0 = blockIdx.x * 32, d0 = blockIdx.y * 32;
#pragma unroll
    for (int i = 0; i < 4; i++) {
        int l = l0 + ty + i * 8;
        t[ty + i * 8][tx] = (l < NLAT) ? lm[(size_t)l * DIM + d0 + tx] * 256.f : 0.f;
    }
    __syncthreads();
#pragma unroll
    for (int i = 0; i < 4; i++) {
        int d = d0 + ty + i * 8;
        g_LT8[(size_t)d * NLATP + l0 + tx] = pack_e4m3(t[tx][ty + i * 8]);
    }
}

// ---------------- GEMM1: E8 = fp8(32*exp((Q8@L8^T)/8192)), fused rowsum ----------------
// CTA 128x128, BK=64 fp8 bytes, 8 warps (4m x 2n), warp 32x64, 4-stage cp.async.

__global__ __launch_bounds__(256, 2) void gemm1_f8() {
    extern __shared__ char dsm[];
    __shared__ float prsum[128][2];

    const int tid = threadIdx.x, lane = tid & 31, wid = tid >> 5;
    const int wm = wid & 3, wn = wid >> 2;
    const int tg = lane >> 2, tig = lane & 3;
    const int bm = blockIdx.y * 128, bn = blockIdx.x * 128;
    const uint32_t smem = (uint32_t)__cvta_generic_to_shared(dsm);

    float c[2][8][4];
#pragma unroll
    for (int i = 0; i < 2; i++)
#pragma unroll
        for (int j = 0; j < 8; j++)
#pragma unroll
            for (int k = 0; k < 4; k++) c[i][j][k] = 0.f;

    const int nk = DIM / 64;   // 8

    auto load_chunk = [&](int cc, int s) {
        int k0 = cc * 64;
        uint32_t sA = smem + s * 20480;
        uint32_t sB = sA + 10240;
#pragma unroll
        for (int i = 0; i < 2; i++) {             // A: 512 chunks of 16B
            int lin = i * 256 + tid;
            int row = lin >> 2, cl = lin & 3;
            cp16(sA + row * 80 + cl * 16,
                 g_Q8 + (size_t)(bm + row) * DIM + k0 + cl * 16, 16);
        }
#pragma unroll
        for (int i = 0; i < 2; i++) {             // B: 512 chunks
            int lin = i * 256 + tid;
            int row = lin >> 2, cl = lin & 3;
            int nrow = bn + row;
            int ok = (nrow < NLAT);
            cp16(sB + row * 80 + cl * 16,
                 g_L8 + (size_t)(ok ? nrow : 0) * DIM + k0 + cl * 16, ok ? 16 : 0);
        }
        CP_COMMIT();
    };

    load_chunk(0, 0); load_chunk(1, 1); load_chunk(2, 2);

    for (int cc = 0; cc < nk; cc++) {
        if (cc + 2 < nk) CP_WAIT2(); else if (cc + 1 < nk) CP_WAIT1(); else CP_WAIT0();
        __syncthreads();
        if (cc + 3 < nk) load_chunk(cc + 3, (cc + 3) & 3);

        int s = cc & 3;
        uint32_t sA = smem + s * 20480;
        uint32_t sB = sA + 10240;
        uint32_t abase = sA + (wm * 32 + (lane & 15)) * 80 + (lane >> 4) * 16;
        uint32_t bbase = sB + (wn * 64 + (lane & 7) + ((lane >> 4) & 1) * 8) * 80
                            + ((lane >> 3) & 1) * 16;
#pragma unroll
        for (int ks = 0; ks < 2; ks++) {
            uint32_t a0[4], a1[4];
            ldsm4(a0, abase + ks * 32);
            ldsm4(a1, abase + 1280 + ks * 32);
#pragma unroll
            for (int j = 0; j < 4; j++) {
                uint32_t b[4];
                ldsm4(b, bbase + j * 1280 + ks * 32);
                mma_e4m3(c[0][2 * j],     a0, b);
                mma_e4m3(c[0][2 * j + 1], a0, b + 2);
                mma_e4m3(c[1][2 * j],     a1, b);
                mma_e4m3(c[1][2 * j + 1], a1, b + 2);
            }
        }
    }

    // Epilogue: poly-exp + fp8 store + fused rowsum.
    float rs[2][2] = {{0.f, 0.f}, {0.f, 0.f}};
#pragma unroll
    for (int mf = 0; mf < 2; mf++) {
        int r0 = bm + wm * 32 + mf * 16 + tg;
        int r1 = r0 + 8;
#pragma unroll
        for (int nf = 0; nf < 8; nf++) {
            int n = bn + wn * 64 + nf * 8 + tig * 2;
            bool v = (n < NLAT);
            float e0 = v ? fast_exp(c[mf][nf][0] * INV_8192) : 0.f;
            float e1 = v ? fast_exp(c[mf][nf][1] * INV_8192) : 0.f;
            float e2 = v ? fast_exp(c[mf][nf][2] * INV_8192) : 0.f;
            float e3 = v ? fast_exp(c[mf][nf][3] * INV_8192) : 0.f;
            rs[mf][0] += e0 + e1;
            rs[mf][1] += e2 + e3;
            *(uint16_t*)(g_E8 + (size_t)r0 * NLATP + n) = pack_e4m3x2(e1 * 32.f, e0 * 32.f);
            *(uint16_t*)(g_E8 + (size_t)r1 * NLATP + n) = pack_e4m3x2(e3 * 32.f, e2 * 32.f);
        }
    }
    // reduce over tig quad (lanes tg*4 + 0..3)
#pragma unroll
    for (int mf = 0; mf < 2; mf++)
#pragma unroll
        for (int h = 0; h < 2; h++) {
            rs[mf][h] += __shfl_xor_sync(0xffffffffu, rs[mf][h], 1);
            rs[mf][h] += __shfl_xor_sync(0xffffffffu, rs[mf][h], 2);
        }
    if (tig == 0) {
#pragma unroll
        for (int mf = 0; mf < 2; mf++) {
            prsum[wm * 32 + mf * 16 + tg][wn]     = rs[mf][0];
            prsum[wm * 32 + mf * 16 + 8 + tg][wn] = rs[mf][1];
        }
    }
    __syncthreads();
    if (tid < 128)
        g_part[(size_t)(bm + tid) * NB1 + blockIdx.x] = prsum[tid][0] + prsum[tid][1];
}

// ---------------- reduce: den ----------------

__global__ void reduce_den() {
    int r = blockIdx.x * blockDim.x + threadIdx.x;
    float s = 0.f;
#pragma unroll
    for (int i = 0; i < NB1; i++) s += g_part[(size_t)r * NB1 + i];
    g_den[r] = s;
}

// ---------------- GEMM2: out = lang + (E8@LT8^T)/8192/den, + token override ----------------
// CTA 128x128 over [tok, d], K = NLATP in 160 chunks of 64.

__global__ __launch_bounds__(256, 2) void gemm2_f8(const int* __restrict__ x,
                                                   const float* __restrict__ ct,
                                                   float* __restrict__ out) {
    extern __shared__ char dsm[];

    const int tid = threadIdx.x, lane = tid & 31, wid = tid >> 5;
    const int wm = wid & 3, wn = wid >> 2;
    const int tg = lane >> 2, tig = lane & 3;
    const int bm = blockIdx.y * 128, bn = blockIdx.x * 128;
    const uint32_t smem = (uint32_t)__cvta_generic_to_shared(dsm);

    float c[2][8][4];
#pragma unroll
    for (int i = 0; i < 2; i++)
#pragma unroll
        for (int j = 0; j < 8; j++)
#pragma unroll
            for (int k = 0; k < 4; k++) c[i][j][k] = 0.f;

    const int nk = NLATP / 64;  // 160

    auto load_chunk = [&](int cc, int s) {
        int k0 = cc * 64;
        uint32_t sA = smem + s * 20480;
        uint32_t sB = sA + 10240;
#pragma unroll
        for (int i = 0; i < 2; i++) {
            int lin = i * 256 + tid;
            int row = lin >> 2, cl = lin & 3;
            cp16(sA + row * 80 + cl * 16,
                 g_E8 + (size_t)(bm + row) * NLATP + k0 + cl * 16, 16);
        }
#pragma unroll
        for (int i = 0; i < 2; i++) {
            int lin = i * 256 + tid;
            int row = lin >> 2, cl = lin & 3;
            cp16(sB + row * 80 + cl * 16,
                 g_LT8 + (size_t)(bn + row) * NLATP + k0 + cl * 16, 16);
        }
        CP_COMMIT();
    };

    load_chunk(0, 0); load_chunk(1, 1); load_chunk(2, 2);

    for (int cc = 0; cc < nk; cc++) {
        if (cc + 2 < nk) CP_WAIT2(); else if (cc + 1 < nk) CP_WAIT1(); else CP_WAIT0();
        __syncthreads();
        if (cc + 3 < nk) load_chunk(cc + 3, (cc + 3) & 3);

        int s = cc & 3;
        uint32_t sA = smem + s * 20480;
        uint32_t sB = sA + 10240;
        uint32_t abase = sA + (wm * 32 + (lane & 15)) * 80 + (lane >> 4) * 16;
        uint32_t bbase = sB + (wn * 64 + (lane & 7) + ((lane >> 4) & 1) * 8) * 80
                            + ((lane >> 3) & 1) * 16;
#pragma unroll
        for (int ks = 0; ks < 2; ks++) {
            uint32_t a0[4], a1[4];
            ldsm4(a0, abase + ks * 32);
            ldsm4(a1, abase + 1280 + ks * 32);
#pragma unroll
            for (int j = 0; j < 4; j++) {
                uint32_t b[4];
                ldsm4(b, bbase + j * 1280 + ks * 32);
                mma_e4m3(c[0][2 * j],     a0, b);
                mma_e4m3(c[0][2 * j + 1], a0, b + 2);
                mma_e4m3(c[1][2 * j],     a1, b);
                mma_e4m3(c[1][2 * j + 1], a1, b + 2);
            }
        }
    }

    // Epilogue: descale, /den, +lang, first-token override. Final output.
#pragma unroll
    for (int mf = 0; mf < 2; mf++) {
        int r0 = bm + wm * 32 + mf * 16 + tg;
        int r1 = r0 + 8;
        float di0 = INV_8192 / g_den[r0];
        float di1 = INV_8192 / g_den[r1];
        unsigned f0 = (unsigned)x[(size_t)r0 * NG];
        unsigned f1 = (unsigned)x[(size_t)r1 * NG];
#pragma unroll
        for (int nf = 0; nf < 8; nf++) {
            int ccol = bn + wn * 64 + nf * 8 + tig * 2;
            float2 o0, o1;
            if (f0 <= 3u) {
                o0.x = ct[(size_t)f0 * DIM + ccol];
                o0.y = ct[(size_t)f0 * DIM + ccol + 1];
            } else {
                o0.x = c[mf][nf][0] * di0 + g_lang[(size_t)r0 * DIM + ccol];
                o0.y = c[mf][nf][1] * di0 + g_lang[(size_t)r0 * DIM + ccol + 1];
            }
            if (f1 <= 3u) {
                o1.x = ct[(size_t)f1 * DIM + ccol];
                o1.y = ct[(size_t)f1 * DIM + ccol + 1];
            } else {
                o1.x = c[mf][nf][2] * di1 + g_lang[(size_t)r1 * DIM + ccol];
                o1.y = c[mf][nf][3] * di1 + g_lang[(size_t)r1 * DIM + ccol + 1];
            }
            *(float2*)(out + (size_t)r0 * DIM + ccol) = o0;
            *(float2*)(out + (size_t)r1 * DIM + ccol) = o1;
        }
    }
}

// ---------------- launch ----------------

#define SMEM_BYTES (4 * 20480)   // 80 KB dynamic

extern "C" void kernel_launch(void* const* d_in, const int* in_sizes, int n_in,
                              void* d_out, int out_size) {
    const int*   x  = (const int*)d_in[0];
    const float* ct = (const float*)d_in[1];
    const float* lm = (const float*)d_in[2];
    float* out = (float*)d_out;

    cudaFuncSetAttribute(gemm1_f8, cudaFuncAttributeMaxDynamicSharedMemorySize, SMEM_BYTES);
    cudaFuncSetAttribute(gemm2_f8, cudaFuncAttributeMaxDynamicSharedMemorySize, SMEM_BYTES);

    lang_kernel<<<NTOK, 128>>>(x, ct);
    cvt_latent8<<<(NLAT * DIM) / (4 * 256), 256>>>(lm);
    transpose_latent8<<<dim3(NLATP / 32, DIM / 32), dim3(32, 8)>>>(lm);
    gemm1_f8<<<dim3(NB1, NTOK / 128), 256, SMEM_BYTES>>>();
    reduce_den<<<NTOK / 256, 256>>>();
    gemm2_f8<<<dim3(DIM / 128, NTOK / 128), 256, SMEM_BYTES>>>(x, ct, out);
}